// round 12
// baseline (speedup 1.0000x reference)
#include <cuda_runtime.h>

// Problem constants
#define BQ    8192
#define NSUB  16
#define KC    1024
#define EDIM  16
#define DEPTHQ 3
#define DIMQ  256
#define EPSC  2e-4f   // shortlist margin; j-dependent rounding bound ~1e-5 (20x margin)

// Output layout: [loss(1), z_q_out(B*256), onehot(B*16*1024), idx(B*16)]
#define OFF_LOSS   ((size_t)0)
#define OFF_ZQ     ((size_t)1)
#define OFF_ONEHOT ((size_t)(1 + BQ * DIMQ))
#define OFF_IDX    ((size_t)(OFF_ONEHOT + (size_t)BQ * NSUB * KC))

__device__ float g_P[(size_t)NSUB * KC * DIMQ];      // 16.8 MB
__device__ int   g_idx[(size_t)BQ * NSUB * DEPTHQ];
__device__ float g_G[(size_t)NSUB * KC * KC];        // 64 MB: 2*<e_k, e_j> per codebook

// 16-step sequential fmaf chain (i = 0..15) — bit-matches the reference contraction
#define CHAIN16(acc, A, B, C, D) do {                               \
    acc = fmaf(zr[0],  (A).x, acc); acc = fmaf(zr[1],  (A).y, acc); \
    acc = fmaf(zr[2],  (A).z, acc); acc = fmaf(zr[3],  (A).w, acc); \
    acc = fmaf(zr[4],  (B).x, acc); acc = fmaf(zr[5],  (B).y, acc); \
    acc = fmaf(zr[6],  (B).z, acc); acc = fmaf(zr[7],  (B).w, acc); \
    acc = fmaf(zr[8],  (C).x, acc); acc = fmaf(zr[9],  (C).y, acc); \
    acc = fmaf(zr[10], (C).z, acc); acc = fmaf(zr[11], (C).w, acc); \
    acc = fmaf(zr[12], (D).x, acc); acc = fmaf(zr[13], (D).y, acc); \
    acc = fmaf(zr[14], (D).z, acc); acc = fmaf(zr[15], (D).w, acc); \
} while (0)

// ---------------- kernel 0: 2*Gram table per codebook ----------------
// grid (16 k1-chunks, 16 n), 1024 threads (j). G accuracy only gates the
// shortlist margin, not exactness.
__global__ void __launch_bounds__(1024, 1)
compute_G_kernel(const float* __restrict__ emb) {
    const int chunk = blockIdx.x;    // 64 k1 values per chunk
    const int n = blockIdx.y;
    const int j = threadIdx.x;

    __shared__ float se[64 * EDIM];
    se[j] = emb[(size_t)n * KC * EDIM + (size_t)chunk * 1024 + j];

    float ej[16];
    const float* ejp = emb + (size_t)n * KC * EDIM + (size_t)j * EDIM;
#pragma unroll
    for (int i = 0; i < 16; i++) ej[i] = ejp[i];
    __syncthreads();

    float* gdst = g_G + ((size_t)n << 20) + ((size_t)chunk * 64 << 10) + j;
#pragma unroll 4
    for (int k = 0; k < 64; k++) {
        float c = 0.0f;
#pragma unroll
        for (int i = 0; i < 16; i++) c = fmaf(se[k * EDIM + i], ej[i], c);
        gdst[(size_t)k << 10] = 2.0f * c;
    }
}

// ---------------- kernel 1: P precompute (+ zero loss slot) ----------------
__global__ void compute_P_kernel(const float* __restrict__ emb,
                                 const float* __restrict__ W,
                                 float* __restrict__ out) {
    if (blockIdx.x == 0 && threadIdx.x == 0) out[OFF_LOSS] = 0.0f;

    const int n  = blockIdx.x >> 6;
    const int k0 = (blockIdx.x & 63) * 16;
    const int j  = threadIdx.x;

    __shared__ float se[16 * EDIM];
    se[j] = emb[((size_t)n * KC + k0) * EDIM + j];

    float w[16];
#pragma unroll
    for (int i = 0; i < 16; i++) w[i] = W[(size_t)(n * 16 + i) * DIMQ + j];
    __syncthreads();

#pragma unroll
    for (int kk = 0; kk < 16; kk++) {
        float acc = 0.0f;
#pragma unroll
        for (int i = 0; i < 16; i++) acc = fmaf(se[kk * EDIM + i], w[i], acc);
        g_P[((size_t)n * KC + (k0 + kk)) * DIMQ + j] = acc;
    }
}

// ---------------- kernel 2: VQ — warp-per-row, Gram-shortlist depths 2/3 ----------------
// grid (64 row-tiles of 128 rows, 16 n), 256 threads = 8 warps, 16 rows/warp.
// SMEM: cb4[4][1024] float4 (dim-major, conflict-free for j = 32t+lane) 64KB
//       + esq[1024] 4KB + sbk[128] ints.
#define VQ_SMEM ((size_t)(4 * KC * 16 + KC * 4 + 128 * 4))

__global__ void __launch_bounds__(256, 2)
vq_kernel(const float* __restrict__ z,
          const float* __restrict__ emb,
          float* __restrict__ out) {
    extern __shared__ float smemf[];
    float4* cb4 = (float4*)smemf;                 // cb4[g*1024 + j] = dims 4g..4g+3 of code j
    float* s_esq = smemf + 4 * KC * 4;            // esq[j]
    int* sbk = (int*)(s_esq + KC);                // last-depth idx per local row

    const int n = blockIdx.y;
    const int rowbase = blockIdx.x * 128;
    const int tid = threadIdx.x;
    const int wid = tid >> 5, lane = tid & 31;

    // Fill codebook (dim-major) + esq (sequential fmaf chain — matches ref)
    for (int j = tid; j < KC; j += 256) {
        const float4* e4 = (const float4*)(emb + ((size_t)n * KC + j) * EDIM);
        float4 a = e4[0], b = e4[1], c = e4[2], dq = e4[3];
        cb4[j] = a; cb4[KC + j] = b; cb4[2 * KC + j] = c; cb4[3 * KC + j] = dq;
        float es = 0.0f;
        es = fmaf(a.x, a.x, es);  es = fmaf(a.y, a.y, es);
        es = fmaf(a.z, a.z, es);  es = fmaf(a.w, a.w, es);
        es = fmaf(b.x, b.x, es);  es = fmaf(b.y, b.y, es);
        es = fmaf(b.z, b.z, es);  es = fmaf(b.w, b.w, es);
        es = fmaf(c.x, c.x, es);  es = fmaf(c.y, c.y, es);
        es = fmaf(c.z, c.z, es);  es = fmaf(c.w, c.w, es);
        es = fmaf(dq.x, dq.x, es); es = fmaf(dq.y, dq.y, es);
        es = fmaf(dq.z, dq.z, es); es = fmaf(dq.w, dq.w, es);
        s_esq[j] = es;
    }
    __syncthreads();

    const float* twoGn = g_G + ((size_t)n << 20);

    for (int r = 0; r < 16; ++r) {
        // Onehot zero-fill slice r (rows r*8..r*8+7 of this tile; overlaps scan)
        {
            const int rr0 = r * 8;
            for (int rr = 0; rr < 8; rr++) {
                float* dst = out + OFF_ONEHOT + ((size_t)(rowbase + rr0 + rr) * NSUB + n) * KC;
                dst[tid] = 0.0f; dst[tid + 256] = 0.0f;
                dst[tid + 512] = 0.0f; dst[tid + 768] = 0.0f;
            }
        }

        const int b = rowbase + wid * 16 + r;
        // Residual (replicated in all lanes) + zsq (sequential chain — matches ref)
        float zr[16];
        float zsq = 0.0f;
        {
            const float4* zp = (const float4*)(z + (size_t)b * DIMQ + n * EDIM);
            float4 z0 = zp[0], z1 = zp[1], z2 = zp[2], z3 = zp[3];
            zr[0] = z0.x; zr[1] = z0.y; zr[2] = z0.z; zr[3] = z0.w;
            zr[4] = z1.x; zr[5] = z1.y; zr[6] = z1.z; zr[7] = z1.w;
            zr[8] = z2.x; zr[9] = z2.y; zr[10] = z2.z; zr[11] = z2.w;
            zr[12] = z3.x; zr[13] = z3.y; zr[14] = z3.z; zr[15] = z3.w;
#pragma unroll
            for (int i = 0; i < 16; i++) zsq = fmaf(zr[i], zr[i], zsq);
        }

        float gs[32];   // scores for codes j = 32t + lane (depth-1 exact chain values)
        int bk = 0;

#pragma unroll 1
        for (int d = 0; d < DEPTHQ; d++) {
            unsigned long long bestkey = 0xFFFFFFFFFFFFFFFFull;

            if (d == 0) {
                // Exact full scan; key = (bits(sqrt(max(s,0))) << 32) | j.
                // uint order == float order for d >= 0; equal d -> lower j:
                // exactly jnp.argmin over d with first-index ties.
#pragma unroll
                for (int t = 0; t < 32; t++) {
                    const int j = t * 32 + lane;
                    float4 A = cb4[j], B = cb4[KC + j], C = cb4[2 * KC + j], D = cb4[3 * KC + j];
                    float c = 0.0f;
                    CHAIN16(c, A, B, C, D);
                    const float s = fmaf(-2.0f, c, zsq) + s_esq[j];
                    gs[t] = s;
                    const float dv = sqrtf(fmaxf(s, 0.0f));
                    const unsigned long long key =
                        ((unsigned long long)__float_as_uint(dv) << 32) | (unsigned)j;
                    bestkey = bestkey < key ? bestkey : key;
                }
            } else {
                // Gram update: gs(j) += 2<e_{bk_prev}, e_j>  (argmin-equivalent up
                // to a j-independent zsq drift). Coalesced 128B per t across lanes.
                const float* grow = twoGn + ((size_t)bk << 10);
#pragma unroll
                for (int t = 0; t < 32; t++) gs[t] += grow[t * 32 + lane];

                // Approx min + shortlist threshold
                float m = gs[0];
#pragma unroll
                for (int t = 1; t < 32; t++) m = fminf(m, gs[t]);
#pragma unroll
                for (int o = 16; o; o >>= 1)
                    m = fminf(m, __shfl_xor_sync(0xffffffffu, m, o));
                const float gthr = m + EPSC;

                // Exact rescore of candidates (expected ~1-3 per row): bit-exact
                // reference chain on the CURRENT residual; u64 key as in depth 0.
#pragma unroll
                for (int t = 0; t < 32; t++) {
                    if (gs[t] <= gthr) {
                        const int j = t * 32 + lane;
                        float4 A = cb4[j], B = cb4[KC + j], C = cb4[2 * KC + j], D = cb4[3 * KC + j];
                        float c = 0.0f;
                        CHAIN16(c, A, B, C, D);
                        const float s = fmaf(-2.0f, c, zsq) + s_esq[j];
                        const float dv = sqrtf(fmaxf(s, 0.0f));
                        const unsigned long long key =
                            ((unsigned long long)__float_as_uint(dv) << 32) | (unsigned)j;
                        bestkey = bestkey < key ? bestkey : key;
                    }
                }
            }

            // Warp argmin reduce (lexicographic (d, j) -> first-index tie-break)
#pragma unroll
            for (int o = 16; o; o >>= 1) {
                unsigned long long ok = __shfl_xor_sync(0xffffffffu, bestkey, o);
                bestkey = bestkey < ok ? bestkey : ok;
            }
            bk = (int)(unsigned)bestkey;

            if (lane == 0) g_idx[((size_t)b * NSUB + n) * DEPTHQ + d] = bk;

            if (d < DEPTHQ - 1) {
                // zr -= e_bk (one fp32 sub per component, matching ref); zsq refresh
                float4 A = cb4[bk], B = cb4[KC + bk], C = cb4[2 * KC + bk], D = cb4[3 * KC + bk];
                zr[0] -= A.x; zr[1] -= A.y; zr[2] -= A.z; zr[3] -= A.w;
                zr[4] -= B.x; zr[5] -= B.y; zr[6] -= B.z; zr[7] -= B.w;
                zr[8] -= C.x; zr[9] -= C.y; zr[10] -= C.z; zr[11] -= C.w;
                zr[12] -= D.x; zr[13] -= D.y; zr[14] -= D.z; zr[15] -= D.w;
                zsq = 0.0f;
#pragma unroll
                for (int i = 0; i < 16; i++) zsq = fmaf(zr[i], zr[i], zsq);
            } else if (lane == 0) {
                out[OFF_IDX + (size_t)b * NSUB + n] = (float)bk;
                sbk[wid * 16 + r] = bk;
            }
        }
    }

    // All zero-fills precede this barrier; ones after.
    __syncthreads();
    if (tid < 128) {
        const int b = rowbase + tid;
        out[OFF_ONEHOT + ((size_t)b * NSUB + n) * KC + sbk[tid]] = 1.0f;
    }
}

// ---------------- kernel 3: z_q gather + z_q_out + loss ----------------
__global__ void gather_out_kernel(const float* __restrict__ z,
                                  const float* __restrict__ bias,
                                  float* __restrict__ out) {
    const int b = blockIdx.x;
    const int j = threadIdx.x;
    __shared__ int sidx[48];
    __shared__ float sred[8];

    if (j < 48) sidx[j] = g_idx[(size_t)b * 48 + j];
    __syncthreads();

    float acc = 0.0f;
#pragma unroll
    for (int n = 0; n < NSUB; n++) {
#pragma unroll
        for (int d = 0; d < DEPTHQ; d++) {
            const int k = sidx[n * 3 + d];
            acc += g_P[(((size_t)n << 10) + k) * DIMQ + j];
        }
    }
    const float zq = acc * (1.0f / 3.0f) + bias[j];
    const float zv = z[(size_t)b * DIMQ + j];
    const float diff = zq - zv;
    out[OFF_ZQ + (size_t)b * DIMQ + j] = zv + diff;

    float p = diff * diff;
#pragma unroll
    for (int off = 16; off > 0; off >>= 1) p += __shfl_down_sync(0xffffffffu, p, off);
    if ((j & 31) == 0) sred[j >> 5] = p;
    __syncthreads();
    if (j == 0) {
        float s = 0.0f;
#pragma unroll
        for (int i = 0; i < 8; i++) s += sred[i];
        atomicAdd(out + OFF_LOSS, s * (1.25f / (float)(BQ * DIMQ)));
    }
}

// ---------------- launcher ----------------
extern "C" void kernel_launch(void* const* d_in, const int* in_sizes, int n_in,
                              void* d_out, int out_size) {
    const float* z    = (const float*)d_in[0];
    const float* emb  = (const float*)d_in[1];
    const float* W    = (const float*)d_in[2];
    const float* bias = (const float*)d_in[3];
    float* out = (float*)d_out;

    (void)in_sizes; (void)n_in; (void)out_size;

    // G table first (vq depends on it; same stream = ordered).
    compute_G_kernel<<<dim3(16, 16), 1024>>>(emb);

    cudaFuncSetAttribute(vq_kernel, cudaFuncAttributeMaxDynamicSharedMemorySize, (int)VQ_SMEM);
    vq_kernel<<<dim3(64, 16), 256, VQ_SMEM>>>(z, emb, out);

    compute_P_kernel<<<1024, 256>>>(emb, W, out);

    gather_out_kernel<<<BQ, 256>>>(z, bias, out);
}